// round 9
// baseline (speedup 1.0000x reference)
#include <cuda_runtime.h>

// VectorKuramoto factorized:
//   sum_j A*sin(tj - ti - a) = ci*P - si*Q
//   P = sum_j (A cos a) sj - (A sin a) cj ; Q = sum_j (A cos a) cj + (A sin a) sj
// R9 = R8 (one-wave balanced grid, pair warps, smem fp32 tables) with the pair
// mainloop unrolled x2: 12 front-batched LDG.128 per iteration for ~2x memory
// latency coverage. 448-thr blocks (launch_bounds(448,2) -> 72-reg budget).

namespace {

constexpr int Bb = 4;
constexpr int Nn = 2048;
constexpr int N4 = Nn / 4;              // 512 float4 per row
constexpr int THREADS = 448;            // 14 warps

__device__ __host__ __forceinline__ int padidx(int i) { return i + (i >> 3); }
constexpr int PAD_N = Nn + (Nn >> 3);   // 2304 float4 slots per table
constexpr int SMEM_BYTES = 2 * PAD_N * (int)sizeof(float4);  // 73728 B

typedef unsigned long long ull;

#define FMA2(d, a, b, c) \
    asm("fma.rn.f32x2 %0, %1, %2, %3;" : "=l"(d) : "l"(a), "l"(b), "l"(c))
#define PACK2(d, lo, hi) \
    asm("mov.b64 %0, {%1, %2};" : "=l"(d) : "f"(lo), "f"(hi))
#define UNPACK2(lo, hi, s) \
    asm("mov.b64 {%0, %1}, %2;" : "=f"(lo), "=f"(hi) : "l"(s))

union F4U { float4 v; ull u[2]; };

__device__ __forceinline__ void cell(float A, float a,
                                     ull sj01, ull sj23, ull cj01, ull cj23,
                                     ull& Pa, ull& Pb, ull& Qa, ull& Qb)
{
    float sa, ca;
    __sincosf(a, &sa, &ca);
    float w1 = A * ca;
    float w2 = A * sa;
    float nw2 = -w2;
    ull pw1, pw2, pnw2;
    PACK2(pw1, w1, w1);
    PACK2(pw2, w2, w2);
    PACK2(pnw2, nw2, nw2);
    FMA2(Pa, pnw2, cj01, Pa); FMA2(Pa, pw1, sj01, Pa);
    FMA2(Pb, pnw2, cj23, Pb); FMA2(Pb, pw1, sj23, Pb);
    FMA2(Qa, pw2,  sj01, Qa); FMA2(Qa, pw1, cj01, Qa);
    FMA2(Qb, pw2,  sj23, Qb); FMA2(Qb, pw1, cj23, Qb);
}

// Consume a 4-j chunk for two rows using shared table reads.
__device__ __forceinline__ void chunk2(const float4* __restrict__ s4,
                                       const float4* __restrict__ c4,
                                       int jb,
                                       const float4& A0, const float4& T0, const float4& B0,
                                       const float4& A1, const float4& T1, const float4& B1,
                                       ull& P0a, ull& P0b, ull& Q0a, ull& Q0b,
                                       ull& P1a, ull& P1b, ull& Q1a, ull& Q1b)
{
    const int j0 = jb << 2;
    F4U sj, cj;
    sj.v = s4[padidx(j0 + 0)]; cj.v = c4[padidx(j0 + 0)];
    cell(A0.x, T0.x + B0.x, sj.u[0], sj.u[1], cj.u[0], cj.u[1], P0a, P0b, Q0a, Q0b);
    cell(A1.x, T1.x + B1.x, sj.u[0], sj.u[1], cj.u[0], cj.u[1], P1a, P1b, Q1a, Q1b);

    sj.v = s4[padidx(j0 + 1)]; cj.v = c4[padidx(j0 + 1)];
    cell(A0.y, T0.y + B0.y, sj.u[0], sj.u[1], cj.u[0], cj.u[1], P0a, P0b, Q0a, Q0b);
    cell(A1.y, T1.y + B1.y, sj.u[0], sj.u[1], cj.u[0], cj.u[1], P1a, P1b, Q1a, Q1b);

    sj.v = s4[padidx(j0 + 2)]; cj.v = c4[padidx(j0 + 2)];
    cell(A0.z, T0.z + B0.z, sj.u[0], sj.u[1], cj.u[0], cj.u[1], P0a, P0b, Q0a, Q0b);
    cell(A1.z, T1.z + B1.z, sj.u[0], sj.u[1], cj.u[0], cj.u[1], P1a, P1b, Q1a, Q1b);

    sj.v = s4[padidx(j0 + 3)]; cj.v = c4[padidx(j0 + 3)];
    cell(A0.w, T0.w + B0.w, sj.u[0], sj.u[1], cj.u[0], cj.u[1], P0a, P0b, Q0a, Q0b);
    cell(A1.w, T1.w + B1.w, sj.u[0], sj.u[1], cj.u[0], cj.u[1], P1a, P1b, Q1a, Q1b);
}

} // namespace

extern "C" __global__ void __launch_bounds__(THREADS, 2)
vector_kuramoto_kernel(const float4* __restrict__ theta4,
                       const float4* __restrict__ gamma4,
                       const float4* __restrict__ aff4,
                       const float4* __restrict__ alpha4,
                       const float4* __restrict__ omega4,
                       const float4* __restrict__ kappa4,
                       const float4* __restrict__ abias4,
                       float4* __restrict__ out4)
{
    extern __shared__ float4 smem[];
    float4* s4 = smem;            // sin(theta[b,r,:]) at padidx(r)
    float4* c4 = smem + PAD_N;    // cos(theta[b,r,:]) at padidx(r)

    const int K    = gridDim.x >> 2;     // CTAs per batch-group (nsm/2)
    const int b    = blockIdx.x & 3;     // batch for this CTA
    const int rank = blockIdx.x >> 2;    // rank within group

    const int tid  = threadIdx.x;
    const int warp = tid >> 5;
    const int lane = tid & 31;

    // Build per-batch sincos table (theta[b,r,:] is one float4, D=4).
    for (int r = tid; r < Nn; r += THREADS) {
        float4 th = theta4[b * Nn + r];
        float4 s, c;
        __sincosf(th.x, &s.x, &c.x);
        __sincosf(th.y, &s.y, &c.y);
        __sincosf(th.z, &s.z, &c.z);
        __sincosf(th.w, &s.w, &c.w);
        s4[padidx(r)] = s;
        c4[padidx(r)] = c;
    }
    __syncthreads();

    // Warp-granular row assignment (per-SM byte totals flat to ~2%).
    const int wg = warp * K + rank;      // 0 .. 14K-1
    const int S  = K * 14;               // warps per group
    const float inv = 1.0f / (float)Nn;  // COUPLING=1, DT=1

    if (wg >= Nn) return;

    const int i0 = wg;
    const int i1 = wg + S;

    if (i1 < Nn) {
        // ---- Pair path, unrolled x2: 12 front-batched LDG.128 per iter. ----
        const int rb0 = ((b << 11) + i0) << 9;   // (b*Nn+i0)*N4
        const int rb1 = ((b << 11) + i1) << 9;
        const int bb0 = i0 << 9;
        const int bb1 = i1 << 9;

        ull P0a = 0, P0b = 0, Q0a = 0, Q0b = 0;
        ull P1a = 0, P1b = 0, Q1a = 0, Q1b = 0;

        #pragma unroll 1
        for (int jb = lane; jb < N4; jb += 64) {
            const int jc = jb + 32;
            // 12 independent LDG.128 issued back-to-back.
            float4 A0a = __ldcs(aff4   + rb0 + jb);
            float4 T0a = __ldcs(alpha4 + rb0 + jb);
            float4 A1a = __ldcs(aff4   + rb1 + jb);
            float4 T1a = __ldcs(alpha4 + rb1 + jb);
            float4 A0b = __ldcs(aff4   + rb0 + jc);
            float4 T0b = __ldcs(alpha4 + rb0 + jc);
            float4 A1b = __ldcs(aff4   + rb1 + jc);
            float4 T1b = __ldcs(alpha4 + rb1 + jc);
            float4 B0a = abias4[bb0 + jb];       // L2-reused across batches
            float4 B1a = abias4[bb1 + jb];
            float4 B0b = abias4[bb0 + jc];
            float4 B1b = abias4[bb1 + jc];

            chunk2(s4, c4, jb, A0a, T0a, B0a, A1a, T1a, B1a,
                   P0a, P0b, Q0a, Q0b, P1a, P1b, Q1a, Q1b);
            chunk2(s4, c4, jc, A0b, T0b, B0b, A1b, T1b, B1b,
                   P0a, P0b, Q0a, Q0b, P1a, P1b, Q1a, Q1b);
        }

        float p0[4], q0[4], p1[4], q1[4];
        UNPACK2(p0[0], p0[1], P0a); UNPACK2(p0[2], p0[3], P0b);
        UNPACK2(q0[0], q0[1], Q0a); UNPACK2(q0[2], q0[3], Q0b);
        UNPACK2(p1[0], p1[1], P1a); UNPACK2(p1[2], p1[3], P1b);
        UNPACK2(q1[0], q1[1], Q1a); UNPACK2(q1[2], q1[3], Q1b);

        #pragma unroll
        for (int off = 16; off; off >>= 1) {
            #pragma unroll
            for (int d = 0; d < 4; ++d) {
                p0[d] += __shfl_down_sync(0xffffffffu, p0[d], off);
                q0[d] += __shfl_down_sync(0xffffffffu, q0[d], off);
                p1[d] += __shfl_down_sync(0xffffffffu, p1[d], off);
                q1[d] += __shfl_down_sync(0xffffffffu, q1[d], off);
            }
        }

        if (lane == 0) {
            {
                const int row = b * Nn + i0;
                float4 th = theta4[row];
                float4 si = s4[padidx(i0)];
                float4 ci = c4[padidx(i0)];
                float4 g  = gamma4[row];
                float4 om = omega4[i0];
                float4 kp = kappa4[i0];
                float4 o;
                o.x = th.x + om.x + kp.x * (g.x - th.x) + inv * (ci.x * p0[0] - si.x * q0[0]);
                o.y = th.y + om.y + kp.y * (g.y - th.y) + inv * (ci.y * p0[1] - si.y * q0[1]);
                o.z = th.z + om.z + kp.z * (g.z - th.z) + inv * (ci.z * p0[2] - si.z * q0[2]);
                o.w = th.w + om.w + kp.w * (g.w - th.w) + inv * (ci.w * p0[3] - si.w * q0[3]);
                out4[row] = o;
            }
            {
                const int row = b * Nn + i1;
                float4 th = theta4[row];
                float4 si = s4[padidx(i1)];
                float4 ci = c4[padidx(i1)];
                float4 g  = gamma4[row];
                float4 om = omega4[i1];
                float4 kp = kappa4[i1];
                float4 o;
                o.x = th.x + om.x + kp.x * (g.x - th.x) + inv * (ci.x * p1[0] - si.x * q1[0]);
                o.y = th.y + om.y + kp.y * (g.y - th.y) + inv * (ci.y * p1[1] - si.y * q1[1]);
                o.z = th.z + om.z + kp.z * (g.z - th.z) + inv * (ci.z * p1[2] - si.z * q1[2]);
                o.w = th.w + om.w + kp.w * (g.w - th.w) + inv * (ci.w * p1[3] - si.w * q1[3]);
                out4[row] = o;
            }
        }
    } else {
        // ---- Single-row path (leftover warps; finish early). ----
        const int row = b * Nn + i0;
        const int rb  = row << 9;
        const int bb  = i0 << 9;

        ull Pa = 0, Pb = 0, Qa = 0, Qb = 0;

        #pragma unroll 1
        for (int jb0 = lane; jb0 < N4; jb0 += 64) {
            const int jb1 = jb0 + 32;
            float4 A0 = __ldcs(aff4   + rb + jb0);
            float4 T0 = __ldcs(alpha4 + rb + jb0);
            float4 A1 = __ldcs(aff4   + rb + jb1);
            float4 T1 = __ldcs(alpha4 + rb + jb1);
            float4 B0 = abias4[bb + jb0];
            float4 B1 = abias4[bb + jb1];

            {
                const int j0 = jb0 << 2;
                F4U sj, cj;
                sj.v = s4[padidx(j0 + 0)]; cj.v = c4[padidx(j0 + 0)];
                cell(A0.x, T0.x + B0.x, sj.u[0], sj.u[1], cj.u[0], cj.u[1], Pa, Pb, Qa, Qb);
                sj.v = s4[padidx(j0 + 1)]; cj.v = c4[padidx(j0 + 1)];
                cell(A0.y, T0.y + B0.y, sj.u[0], sj.u[1], cj.u[0], cj.u[1], Pa, Pb, Qa, Qb);
                sj.v = s4[padidx(j0 + 2)]; cj.v = c4[padidx(j0 + 2)];
                cell(A0.z, T0.z + B0.z, sj.u[0], sj.u[1], cj.u[0], cj.u[1], Pa, Pb, Qa, Qb);
                sj.v = s4[padidx(j0 + 3)]; cj.v = c4[padidx(j0 + 3)];
                cell(A0.w, T0.w + B0.w, sj.u[0], sj.u[1], cj.u[0], cj.u[1], Pa, Pb, Qa, Qb);
            }
            {
                const int j1 = jb1 << 2;
                F4U sj, cj;
                sj.v = s4[padidx(j1 + 0)]; cj.v = c4[padidx(j1 + 0)];
                cell(A1.x, T1.x + B1.x, sj.u[0], sj.u[1], cj.u[0], cj.u[1], Pa, Pb, Qa, Qb);
                sj.v = s4[padidx(j1 + 1)]; cj.v = c4[padidx(j1 + 1)];
                cell(A1.y, T1.y + B1.y, sj.u[0], sj.u[1], cj.u[0], cj.u[1], Pa, Pb, Qa, Qb);
                sj.v = s4[padidx(j1 + 2)]; cj.v = c4[padidx(j1 + 2)];
                cell(A1.z, T1.z + B1.z, sj.u[0], sj.u[1], cj.u[0], cj.u[1], Pa, Pb, Qa, Qb);
                sj.v = s4[padidx(j1 + 3)]; cj.v = c4[padidx(j1 + 3)];
                cell(A1.w, T1.w + B1.w, sj.u[0], sj.u[1], cj.u[0], cj.u[1], Pa, Pb, Qa, Qb);
            }
        }

        float p[4], q[4];
        UNPACK2(p[0], p[1], Pa); UNPACK2(p[2], p[3], Pb);
        UNPACK2(q[0], q[1], Qa); UNPACK2(q[2], q[3], Qb);

        #pragma unroll
        for (int off = 16; off; off >>= 1) {
            #pragma unroll
            for (int d = 0; d < 4; ++d) {
                p[d] += __shfl_down_sync(0xffffffffu, p[d], off);
                q[d] += __shfl_down_sync(0xffffffffu, q[d], off);
            }
        }

        if (lane == 0) {
            float4 th = theta4[row];
            float4 si = s4[padidx(i0)];
            float4 ci = c4[padidx(i0)];
            float4 g  = gamma4[row];
            float4 om = omega4[i0];
            float4 kp = kappa4[i0];
            float4 o;
            o.x = th.x + om.x + kp.x * (g.x - th.x) + inv * (ci.x * p[0] - si.x * q[0]);
            o.y = th.y + om.y + kp.y * (g.y - th.y) + inv * (ci.y * p[1] - si.y * q[1]);
            o.z = th.z + om.z + kp.z * (g.z - th.z) + inv * (ci.z * p[2] - si.z * q[2]);
            o.w = th.w + om.w + kp.w * (g.w - th.w) + inv * (ci.w * p[3] - si.w * q[3]);
            out4[row] = o;
        }
    }
}

extern "C" void kernel_launch(void* const* d_in, const int* in_sizes, int n_in,
                              void* d_out, int out_size) {
    (void)in_sizes; (void)n_in; (void)out_size;
    const float4* theta4 = (const float4*)d_in[0];
    const float4* gamma4 = (const float4*)d_in[1];
    const float4* aff4   = (const float4*)d_in[2];
    const float4* alpha4 = (const float4*)d_in[3];
    const float4* omega4 = (const float4*)d_in[4];
    const float4* kappa4 = (const float4*)d_in[5];
    const float4* abias4 = (const float4*)d_in[6];
    float4* out4 = (float4*)d_out;

    static int nsm = 0;
    if (nsm == 0) {
        cudaDeviceProp prop;
        if (cudaGetDeviceProperties(&prop, 0) == cudaSuccess && prop.multiProcessorCount > 0)
            nsm = prop.multiProcessorCount;
        else
            nsm = 148;
        cudaFuncSetAttribute(vector_kuramoto_kernel,
                             cudaFuncAttributeMaxDynamicSharedMemorySize, SMEM_BYTES);
    }

    const int grid = 4 * (nsm / 2);   // 2 CTAs/SM, one uniform wave
    vector_kuramoto_kernel<<<grid, THREADS, SMEM_BYTES>>>(
        theta4, gamma4, aff4, alpha4, omega4, kappa4, abias4, out4);
}

// round 10
// speedup vs baseline: 1.5837x; 1.5837x over previous
#include <cuda_runtime.h>

// VectorKuramoto factorized:
//   sum_j A*sin(tj - ti - a) = ci*P - si*Q
//   P = sum_j (A cos a) sj - (A sin a) cj ; Q = sum_j (A cos a) cj + (A sin a) sj
// R10 = R8 (one-wave balanced grid 304x512, pair warps, smem fp32 tables,
// 6 front-batched LDG.128/iter) + prefetch.global.L2 of next iteration's
// stream lines (register-free latency reduction) + padidx strength reduction.

namespace {

constexpr int Bb = 4;
constexpr int Nn = 2048;
constexpr int N4 = Nn / 4;              // 512 float4 per row
constexpr int THREADS = 512;            // 16 warps

__device__ __host__ __forceinline__ int padidx(int i) { return i + (i >> 3); }
constexpr int PAD_N = Nn + (Nn >> 3);   // 2304 float4 slots per table
constexpr int SMEM_BYTES = 2 * PAD_N * (int)sizeof(float4);  // 73728 B

typedef unsigned long long ull;

#define FMA2(d, a, b, c) \
    asm("fma.rn.f32x2 %0, %1, %2, %3;" : "=l"(d) : "l"(a), "l"(b), "l"(c))
#define PACK2(d, lo, hi) \
    asm("mov.b64 %0, {%1, %2};" : "=l"(d) : "f"(lo), "f"(hi))
#define UNPACK2(lo, hi, s) \
    asm("mov.b64 {%0, %1}, %2;" : "=f"(lo), "=f"(hi) : "l"(s))
#define PREF_L2(p) \
    asm volatile("prefetch.global.L2 [%0];" :: "l"(p))

union F4U { float4 v; ull u[2]; };

__device__ __forceinline__ void cell(float A, float a,
                                     ull sj01, ull sj23, ull cj01, ull cj23,
                                     ull& Pa, ull& Pb, ull& Qa, ull& Qb)
{
    float sa, ca;
    __sincosf(a, &sa, &ca);
    float w1 = A * ca;
    float w2 = A * sa;
    float nw2 = -w2;
    ull pw1, pw2, pnw2;
    PACK2(pw1, w1, w1);
    PACK2(pw2, w2, w2);
    PACK2(pnw2, nw2, nw2);
    FMA2(Pa, pnw2, cj01, Pa); FMA2(Pa, pw1, sj01, Pa);
    FMA2(Pb, pnw2, cj23, Pb); FMA2(Pb, pw1, sj23, Pb);
    FMA2(Qa, pw2,  sj01, Qa); FMA2(Qa, pw1, cj01, Qa);
    FMA2(Qb, pw2,  sj23, Qb); FMA2(Qb, pw1, cj23, Qb);
}

} // namespace

extern "C" __global__ void __launch_bounds__(THREADS, 2)
vector_kuramoto_kernel(const float4* __restrict__ theta4,
                       const float4* __restrict__ gamma4,
                       const float4* __restrict__ aff4,
                       const float4* __restrict__ alpha4,
                       const float4* __restrict__ omega4,
                       const float4* __restrict__ kappa4,
                       const float4* __restrict__ abias4,
                       float4* __restrict__ out4)
{
    extern __shared__ float4 smem[];
    float4* s4 = smem;            // sin(theta[b,r,:]) at padidx(r)
    float4* c4 = smem + PAD_N;    // cos(theta[b,r,:]) at padidx(r)

    const int K    = gridDim.x >> 2;     // CTAs per batch-group (nsm/2)
    const int b    = blockIdx.x & 3;     // batch for this CTA
    const int rank = blockIdx.x >> 2;    // rank within group

    const int tid  = threadIdx.x;
    const int warp = tid >> 5;
    const int lane = tid & 31;

    // Build per-batch sincos table (theta[b,r,:] is one float4, D=4).
    for (int r = tid; r < Nn; r += THREADS) {
        float4 th = theta4[b * Nn + r];
        float4 s, c;
        __sincosf(th.x, &s.x, &c.x);
        __sincosf(th.y, &s.y, &c.y);
        __sincosf(th.z, &s.z, &c.z);
        __sincosf(th.w, &s.w, &c.w);
        s4[padidx(r)] = s;
        c4[padidx(r)] = c;
    }
    __syncthreads();

    // Warp-granular row assignment (per-SM byte totals flat to ~2%).
    const int wg = warp * K + rank;      // 0 .. 16K-1
    const int S  = K << 4;               // 16K warps per group
    const float inv = 1.0f / (float)Nn;  // COUPLING=1, DT=1

    if (wg >= Nn) return;

    const int i0 = wg;
    const int i1 = wg + S;

    if (i1 < Nn) {
        // ---- Pair path: 2 rows share every table read (16 B/cell LDS). ----
        const int rb0 = ((b << 11) + i0) << 9;   // (b*Nn+i0)*N4
        const int rb1 = ((b << 11) + i1) << 9;
        const int bb0 = i0 << 9;
        const int bb1 = i1 << 9;

        ull P0a = 0, P0b = 0, Q0a = 0, Q0b = 0;
        ull P1a = 0, P1b = 0, Q1a = 0, Q1b = 0;

        #pragma unroll 1
        for (int jb = lane; jb < N4; jb += 32) {
            // Front-batched coalesced LDG.128 (streams evict-first).
            float4 A0 = __ldcs(aff4   + rb0 + jb);
            float4 T0 = __ldcs(alpha4 + rb0 + jb);
            float4 B0 = abias4[bb0 + jb];
            float4 A1 = __ldcs(aff4   + rb1 + jb);
            float4 T1 = __ldcs(alpha4 + rb1 + jb);
            float4 B1 = abias4[bb1 + jb];

            // Register-free latency reduction: stage next iteration's stream
            // lines into L2 while this iteration computes.
            const int jn = jb + 32;
            if (jn < N4) {
                PREF_L2(aff4   + rb0 + jn);
                PREF_L2(alpha4 + rb0 + jn);
                PREF_L2(aff4   + rb1 + jn);
                PREF_L2(alpha4 + rb1 + jn);
            }

            // padidx(j0+k) == padidx(j0)+k for k<4 when j0 % 4 == 0.
            const int pb = padidx(jb << 2);
            F4U sj, cj;
            sj.v = s4[pb + 0]; cj.v = c4[pb + 0];
            cell(A0.x, T0.x + B0.x, sj.u[0], sj.u[1], cj.u[0], cj.u[1], P0a, P0b, Q0a, Q0b);
            cell(A1.x, T1.x + B1.x, sj.u[0], sj.u[1], cj.u[0], cj.u[1], P1a, P1b, Q1a, Q1b);

            sj.v = s4[pb + 1]; cj.v = c4[pb + 1];
            cell(A0.y, T0.y + B0.y, sj.u[0], sj.u[1], cj.u[0], cj.u[1], P0a, P0b, Q0a, Q0b);
            cell(A1.y, T1.y + B1.y, sj.u[0], sj.u[1], cj.u[0], cj.u[1], P1a, P1b, Q1a, Q1b);

            sj.v = s4[pb + 2]; cj.v = c4[pb + 2];
            cell(A0.z, T0.z + B0.z, sj.u[0], sj.u[1], cj.u[0], cj.u[1], P0a, P0b, Q0a, Q0b);
            cell(A1.z, T1.z + B1.z, sj.u[0], sj.u[1], cj.u[0], cj.u[1], P1a, P1b, Q1a, Q1b);

            sj.v = s4[pb + 3]; cj.v = c4[pb + 3];
            cell(A0.w, T0.w + B0.w, sj.u[0], sj.u[1], cj.u[0], cj.u[1], P0a, P0b, Q0a, Q0b);
            cell(A1.w, T1.w + B1.w, sj.u[0], sj.u[1], cj.u[0], cj.u[1], P1a, P1b, Q1a, Q1b);
        }

        float p0[4], q0[4], p1[4], q1[4];
        UNPACK2(p0[0], p0[1], P0a); UNPACK2(p0[2], p0[3], P0b);
        UNPACK2(q0[0], q0[1], Q0a); UNPACK2(q0[2], q0[3], Q0b);
        UNPACK2(p1[0], p1[1], P1a); UNPACK2(p1[2], p1[3], P1b);
        UNPACK2(q1[0], q1[1], Q1a); UNPACK2(q1[2], q1[3], Q1b);

        #pragma unroll
        for (int off = 16; off; off >>= 1) {
            #pragma unroll
            for (int d = 0; d < 4; ++d) {
                p0[d] += __shfl_down_sync(0xffffffffu, p0[d], off);
                q0[d] += __shfl_down_sync(0xffffffffu, q0[d], off);
                p1[d] += __shfl_down_sync(0xffffffffu, p1[d], off);
                q1[d] += __shfl_down_sync(0xffffffffu, q1[d], off);
            }
        }

        if (lane == 0) {
            {
                const int row = b * Nn + i0;
                float4 th = theta4[row];
                float4 si = s4[padidx(i0)];
                float4 ci = c4[padidx(i0)];
                float4 g  = gamma4[row];
                float4 om = omega4[i0];
                float4 kp = kappa4[i0];
                float4 o;
                o.x = th.x + om.x + kp.x * (g.x - th.x) + inv * (ci.x * p0[0] - si.x * q0[0]);
                o.y = th.y + om.y + kp.y * (g.y - th.y) + inv * (ci.y * p0[1] - si.y * q0[1]);
                o.z = th.z + om.z + kp.z * (g.z - th.z) + inv * (ci.z * p0[2] - si.z * q0[2]);
                o.w = th.w + om.w + kp.w * (g.w - th.w) + inv * (ci.w * p0[3] - si.w * q0[3]);
                out4[row] = o;
            }
            {
                const int row = b * Nn + i1;
                float4 th = theta4[row];
                float4 si = s4[padidx(i1)];
                float4 ci = c4[padidx(i1)];
                float4 g  = gamma4[row];
                float4 om = omega4[i1];
                float4 kp = kappa4[i1];
                float4 o;
                o.x = th.x + om.x + kp.x * (g.x - th.x) + inv * (ci.x * p1[0] - si.x * q1[0]);
                o.y = th.y + om.y + kp.y * (g.y - th.y) + inv * (ci.y * p1[1] - si.y * q1[1]);
                o.z = th.z + om.z + kp.z * (g.z - th.z) + inv * (ci.z * p1[2] - si.z * q1[2]);
                o.w = th.w + om.w + kp.w * (g.w - th.w) + inv * (ci.w * p1[3] - si.w * q1[3]);
                out4[row] = o;
            }
        }
    } else {
        // ---- Single-row path (leftover warps; finish early). ----
        const int row = b * Nn + i0;
        const int rb  = row << 9;
        const int bb  = i0 << 9;

        ull Pa = 0, Pb = 0, Qa = 0, Qb = 0;

        #pragma unroll 1
        for (int jb0 = lane; jb0 < N4; jb0 += 64) {
            const int jb1 = jb0 + 32;
            float4 A0 = __ldcs(aff4   + rb + jb0);
            float4 T0 = __ldcs(alpha4 + rb + jb0);
            float4 A1 = __ldcs(aff4   + rb + jb1);
            float4 T1 = __ldcs(alpha4 + rb + jb1);
            float4 B0 = abias4[bb + jb0];
            float4 B1 = abias4[bb + jb1];

            const int jn = jb0 + 64;
            if (jn < N4) {
                PREF_L2(aff4   + rb + jn);
                PREF_L2(alpha4 + rb + jn);
                PREF_L2(aff4   + rb + jn + 32);
                PREF_L2(alpha4 + rb + jn + 32);
            }

            {
                const int pb = padidx(jb0 << 2);
                F4U sj, cj;
                sj.v = s4[pb + 0]; cj.v = c4[pb + 0];
                cell(A0.x, T0.x + B0.x, sj.u[0], sj.u[1], cj.u[0], cj.u[1], Pa, Pb, Qa, Qb);
                sj.v = s4[pb + 1]; cj.v = c4[pb + 1];
                cell(A0.y, T0.y + B0.y, sj.u[0], sj.u[1], cj.u[0], cj.u[1], Pa, Pb, Qa, Qb);
                sj.v = s4[pb + 2]; cj.v = c4[pb + 2];
                cell(A0.z, T0.z + B0.z, sj.u[0], sj.u[1], cj.u[0], cj.u[1], Pa, Pb, Qa, Qb);
                sj.v = s4[pb + 3]; cj.v = c4[pb + 3];
                cell(A0.w, T0.w + B0.w, sj.u[0], sj.u[1], cj.u[0], cj.u[1], Pa, Pb, Qa, Qb);
            }
            {
                const int pb = padidx(jb1 << 2);
                F4U sj, cj;
                sj.v = s4[pb + 0]; cj.v = c4[pb + 0];
                cell(A1.x, T1.x + B1.x, sj.u[0], sj.u[1], cj.u[0], cj.u[1], Pa, Pb, Qa, Qb);
                sj.v = s4[pb + 1]; cj.v = c4[pb + 1];
                cell(A1.y, T1.y + B1.y, sj.u[0], sj.u[1], cj.u[0], cj.u[1], Pa, Pb, Qa, Qb);
                sj.v = s4[pb + 2]; cj.v = c4[pb + 2];
                cell(A1.z, T1.z + B1.z, sj.u[0], sj.u[1], cj.u[0], cj.u[1], Pa, Pb, Qa, Qb);
                sj.v = s4[pb + 3]; cj.v = c4[pb + 3];
                cell(A1.w, T1.w + B1.w, sj.u[0], sj.u[1], cj.u[0], cj.u[1], Pa, Pb, Qa, Qb);
            }
        }

        float p[4], q[4];
        UNPACK2(p[0], p[1], Pa); UNPACK2(p[2], p[3], Pb);
        UNPACK2(q[0], q[1], Qa); UNPACK2(q[2], q[3], Qb);

        #pragma unroll
        for (int off = 16; off; off >>= 1) {
            #pragma unroll
            for (int d = 0; d < 4; ++d) {
                p[d] += __shfl_down_sync(0xffffffffu, p[d], off);
                q[d] += __shfl_down_sync(0xffffffffu, q[d], off);
            }
        }

        if (lane == 0) {
            float4 th = theta4[row];
            float4 si = s4[padidx(i0)];
            float4 ci = c4[padidx(i0)];
            float4 g  = gamma4[row];
            float4 om = omega4[i0];
            float4 kp = kappa4[i0];
            float4 o;
            o.x = th.x + om.x + kp.x * (g.x - th.x) + inv * (ci.x * p[0] - si.x * q[0]);
            o.y = th.y + om.y + kp.y * (g.y - th.y) + inv * (ci.y * p[1] - si.y * q[1]);
            o.z = th.z + om.z + kp.z * (g.z - th.z) + inv * (ci.z * p[2] - si.z * q[2]);
            o.w = th.w + om.w + kp.w * (g.w - th.w) + inv * (ci.w * p[3] - si.w * q[3]);
            out4[row] = o;
        }
    }
}

extern "C" void kernel_launch(void* const* d_in, const int* in_sizes, int n_in,
                              void* d_out, int out_size) {
    (void)in_sizes; (void)n_in; (void)out_size;
    const float4* theta4 = (const float4*)d_in[0];
    const float4* gamma4 = (const float4*)d_in[1];
    const float4* aff4   = (const float4*)d_in[2];
    const float4* alpha4 = (const float4*)d_in[3];
    const float4* omega4 = (const float4*)d_in[4];
    const float4* kappa4 = (const float4*)d_in[5];
    const float4* abias4 = (const float4*)d_in[6];
    float4* out4 = (float4*)d_out;

    static int nsm = 0;
    if (nsm == 0) {
        cudaDeviceProp prop;
        if (cudaGetDeviceProperties(&prop, 0) == cudaSuccess && prop.multiProcessorCount > 0)
            nsm = prop.multiProcessorCount;
        else
            nsm = 148;
        cudaFuncSetAttribute(vector_kuramoto_kernel,
                             cudaFuncAttributeMaxDynamicSharedMemorySize, SMEM_BYTES);
    }

    const int grid = 4 * (nsm / 2);   // 2 CTAs/SM, one uniform wave
    vector_kuramoto_kernel<<<grid, THREADS, SMEM_BYTES>>>(
        theta4, gamma4, aff4, alpha4, omega4, kappa4, abias4, out4);
}